// round 16
// baseline (speedup 1.0000x reference)
#include <cuda_runtime.h>
#include <cuda_fp16.h>
#include <cstdint>

// Problem shape (fixed by setup_inputs)
#define BB 4
#define NQ 4096
#define NK 4096
#define DD 128
#define NSPLIT 4
#define CHUNKS_PER_SPLIT (NK / 64 / NSPLIT)   // 16
#define NGROUP (BB * NQ / 64)                 // 256 (b, q0) groups

// Scratch (device globals: allocation-free rule)
__device__ __align__(16) __half g_qh[(size_t)BB * NQ * DD];   // normalized Q, fp16
__device__ __align__(16) __half g_kh[(size_t)BB * NK * DD];   // normalized K, fp16
__device__ __align__(16) __half g_vt[(size_t)BB * DD * NK];   // V transposed [b][d][k], fp16
__device__ __align__(16) __half g_sraw[(size_t)BB * NQ * NK]; // unnormalized p, fp16
__device__ __align__(16) float  g_opart[(size_t)NSPLIT * BB * NQ * DD]; // unnormalized partial O
__device__ float g_lpart[(size_t)NSPLIT * BB * NQ];           // partial row sums
__device__ int   g_ctr[NGROUP];                               // split-completion semaphores

// ---------------------------------------------------------------------------
// K1: L2-normalize q and k rows (warp per row), write fp16.
// Block 0 also re-zeroes the split semaphores (graph-replay safe).
// ---------------------------------------------------------------------------
__global__ void prep_kernel(const float* __restrict__ q, const float* __restrict__ k) {
    if (blockIdx.x == 0 && threadIdx.x < NGROUP) g_ctr[threadIdx.x] = 0;

    int gw   = (blockIdx.x * blockDim.x + threadIdx.x) >> 5;
    int lane = threadIdx.x & 31;
    const int R = BB * NQ;
    if (gw >= 2 * R) return;
    const float* src = (gw < R) ? q : k;
    __half*      dst = (gw < R) ? g_qh : g_kh;
    int row = (gw < R) ? gw : gw - R;

    float4 x = reinterpret_cast<const float4*>(src + (size_t)row * DD)[lane];
    float ss = x.x * x.x + x.y * x.y + x.z * x.z + x.w * x.w;
    #pragma unroll
    for (int o = 16; o; o >>= 1) ss += __shfl_xor_sync(0xffffffffu, ss, o);
    float sc = 1.0f / fmaxf(sqrtf(ss), 1e-12f);

    __half2* dp = reinterpret_cast<__half2*>(dst + (size_t)row * DD);
    dp[lane * 2 + 0] = __floats2half2_rn(x.x * sc, x.y * sc);
    dp[lane * 2 + 1] = __floats2half2_rn(x.z * sc, x.w * sc);
}

// ---------------------------------------------------------------------------
// K1b: transpose V (fp32 [b][k][d]) -> g_vt fp16 [b][d][k], tiles of 64 k-rows
// ---------------------------------------------------------------------------
__global__ void vtrans_kernel(const float* __restrict__ v) {
    __shared__ __half st[128][72];
    int b  = blockIdx.y;
    int k0 = blockIdx.x * 64;
    int t  = threadIdx.x;
    int kr = t >> 2, seg = t & 3;

    const float4* src = reinterpret_cast<const float4*>(v + ((size_t)b * NK + k0 + kr) * DD);
    #pragma unroll
    for (int i = 0; i < 8; i++) {
        float4 f = src[seg * 8 + i];
        int d = seg * 32 + i * 4;
        st[d + 0][kr] = __float2half_rn(f.x);
        st[d + 1][kr] = __float2half_rn(f.y);
        st[d + 2][kr] = __float2half_rn(f.z);
        st[d + 3][kr] = __float2half_rn(f.w);
    }
    __syncthreads();

    int d = t >> 1, j = t & 1;
    uint4*       dst = reinterpret_cast<uint4*>(g_vt + ((size_t)(b * 128 + d)) * NK + k0);
    const uint4* s4  = reinterpret_cast<const uint4*>(&st[d][j * 32]);
    #pragma unroll
    for (int i = 0; i < 4; i++) dst[j * 4 + i] = s4[i];
}

// ---------------------------------------------------------------------------
// PTX helpers
// ---------------------------------------------------------------------------
__device__ __forceinline__ void mma16816(float* d, unsigned a0, unsigned a1, unsigned a2,
                                         unsigned a3, unsigned b0, unsigned b1) {
    asm volatile(
        "mma.sync.aligned.m16n8k16.row.col.f32.f16.f16.f32 "
        "{%0,%1,%2,%3},{%4,%5,%6,%7},{%8,%9},{%0,%1,%2,%3};\n"
        : "+f"(d[0]), "+f"(d[1]), "+f"(d[2]), "+f"(d[3])
        : "r"(a0), "r"(a1), "r"(a2), "r"(a3), "r"(b0), "r"(b1));
}

__device__ __forceinline__ void ldsm4(unsigned& r0, unsigned& r1, unsigned& r2, unsigned& r3,
                                      uint32_t a) {
    asm volatile("ldmatrix.sync.aligned.m8n8.x4.shared.b16 {%0,%1,%2,%3},[%4];\n"
                 : "=r"(r0), "=r"(r1), "=r"(r2), "=r"(r3) : "r"(a));
}

__device__ __forceinline__ void cp16(uint32_t dst, const void* src) {
    asm volatile("cp.async.cg.shared.global [%0], [%1], 16;\n" :: "r"(dst), "l"(src));
}
__device__ __forceinline__ void cp_commit() {
    asm volatile("cp.async.commit_group;\n");
}
__device__ __forceinline__ void cp_wait1() {
    asm volatile("cp.async.wait_group 1;\n");
}

// ---------------------------------------------------------------------------
// K2: fused attention (R6 mainloop) with split-K and a SELF-FINALIZING
// epilogue: split index lives in blockIdx.x so a group's 4 CTAs run in the
// same wave; the last CTA to finish (per-group semaphore) combines the O/l
// partials and normalizes the group's 64 attn rows in place — the 435 MB of
// reduce+finalize traffic overlaps other groups' tensor work.
// ---------------------------------------------------------------------------
#define KS_HALF (64 * 136)     // one K buffer, halves
#define VS_HALF (128 * 72)     // one V buffer, halves
#define SMEM_BYTES 99072       // + sm_rl

__global__ void __launch_bounds__(256, 2)
attn_kernel(const int* __restrict__ mask, const float* __restrict__ temp,
            float* __restrict__ outp, float* __restrict__ attnp) {
    extern __shared__ char smem_raw[];
    __half* Qs = reinterpret_cast<__half*>(smem_raw);     // [64][136]
    __half* Ks = Qs + 64 * 136;                           // 2 x [64][136]
    __half* Vs = Ks + 2 * KS_HALF;                        // 2 x [128][72] (Vs[d][k])
    __half* Ps = Vs + 2 * VS_HALF;                        // [64][72]
    float*  sm_l  = reinterpret_cast<float*>(Ps + 64 * 72); // [2][64]
    float*  sm_rl = sm_l + 128;                           // [64]

    const int z  = blockIdx.x;            // split index (fastest-varying)
    const int q0 = blockIdx.y * 64;
    const int b  = blockIdx.z;
    const int gid = b * (NQ / 64) + blockIdx.y;
    const int c0 = z * CHUNKS_PER_SPLIT;
    const int c1 = c0 + CHUNKS_PER_SPLIT;
    const int tid  = threadIdx.x;
    const int lane = tid & 31;
    const int warp = tid >> 5;
    const int wm = warp & 3;     // 4 warps along M
    const int wn = warp >> 2;    // 2 warps along N
    const int lg = lane >> 2;    // group id 0..7
    const int lq = lane & 3;     // quad id 0..3

    const float invt = 1.0f / temp[0];

    // Load Q tile (fp16) once
    {
        int r = tid >> 2, seg = tid & 3;
        const uint4* src = reinterpret_cast<const uint4*>(g_qh + ((size_t)b * NQ + q0 + r) * DD);
        uint4* dst = reinterpret_cast<uint4*>(&Qs[r * 136 + seg * 32]);
        #pragma unroll
        for (int i = 0; i < 4; i++) dst[i] = src[seg * 4 + i];
    }

    // ldmatrix per-lane base addresses
    const int lrow = lane & 15;
    const int lcol = (lane >> 4) << 3;
    const uint32_t a_q  = (uint32_t)__cvta_generic_to_shared(&Qs[(wm * 16 + lrow) * 136 + lcol]);
    const uint32_t b_k0 = (uint32_t)__cvta_generic_to_shared(&Ks[(wn * 32 + lrow) * 136 + lcol]);
    const uint32_t b_k1 = (uint32_t)__cvta_generic_to_shared(&Ks[(wn * 32 + 16 + lrow) * 136 + lcol]);
    const uint32_t a_p  = (uint32_t)__cvta_generic_to_shared(&Ps[(wm * 16 + lrow) * 72 + lcol]);
    uint32_t b_v[4];
    #pragma unroll
    for (int p = 0; p < 4; p++)
        b_v[p] = (uint32_t)__cvta_generic_to_shared(&Vs[(wn * 64 + p * 16 + lrow) * 72 + lcol]);

    // cp.async staging addresses
    const int kr  = tid >> 2, kseg = tid & 3;
    const uint32_t ks_dst = (uint32_t)__cvta_generic_to_shared(&Ks[kr * 136 + kseg * 32]);
    const int vd = tid >> 1, vj = tid & 1;
    const uint32_t vs_dst = (uint32_t)__cvta_generic_to_shared(&Vs[vd * 72 + vj * 32]);

    const __half* gk  = g_kh + (size_t)b * NK * DD;
    const __half* gvt = g_vt + ((size_t)b * DD + vd) * NK;

    const int grow0 = q0 + wm * 16 + lg;
    const size_t rbase0 = ((size_t)b * NQ + grow0) * NK;
    const size_t rbase1 = rbase0 + (size_t)8 * NK;

    float oacc[8][4];
    #pragma unroll
    for (int t = 0; t < 8; t++)
        #pragma unroll
        for (int r = 0; r < 4; r++) oacc[t][r] = 0.0f;
    float lsum0 = 0.0f, lsum1 = 0.0f;

    // --- pipeline prologue: load chunk c0 into buffer 0 (c0 is even) ---
    {
        const __half* srcK = gk + (size_t)(c0 * 64 + kr) * DD + kseg * 32;
        #pragma unroll
        for (int i = 0; i < 4; i++) cp16(ks_dst + i * 16, srcK + i * 8);
        const __half* srcV = gvt + c0 * 64 + vj * 32;
        #pragma unroll
        for (int i = 0; i < 4; i++) cp16(vs_dst + i * 16, srcV + i * 8);
        cp_commit();
    }

    for (int c = c0; c < c1; ++c) {
        const int cur = c & 1;
        const uint32_t koff = (uint32_t)cur * (KS_HALF * 2);   // byte offsets
        const uint32_t voff = (uint32_t)cur * (VS_HALF * 2);

        __syncthreads();   // B1: buffer cur^1 free

        // --- issue loads for chunk c+1 into buffer cur^1 ---
        if (c + 1 < c1) {
            const uint32_t nkoff = (uint32_t)(cur ^ 1) * (KS_HALF * 2);
            const uint32_t nvoff = (uint32_t)(cur ^ 1) * (VS_HALF * 2);
            const __half* srcK = gk + (size_t)((c + 1) * 64 + kr) * DD + kseg * 32;
            #pragma unroll
            for (int i = 0; i < 4; i++) cp16(ks_dst + nkoff + i * 16, srcK + i * 8);
            const __half* srcV = gvt + (c + 1) * 64 + vj * 32;
            #pragma unroll
            for (int i = 0; i < 4; i++) cp16(vs_dst + nvoff + i * 16, srcV + i * 8);
        }
        cp_commit();

        // --- prefetch mask for chunk c while loads fly ---
        int2 mk0[4], mk1[4];
        #pragma unroll
        for (int nt = 0; nt < 4; ++nt) {
            const int gcol = c * 64 + wn * 32 + nt * 8 + lq * 2;
            mk0[nt] = *reinterpret_cast<const int2*>(mask + rbase0 + gcol);
            mk1[nt] = *reinterpret_cast<const int2*>(mask + rbase1 + gcol);
        }

        cp_wait1();          // chunk c resident (FIFO group completion)
        __syncthreads();     // B2: visibility across threads

        // --- S = Qn @ Kn^T : warp computes 16x32 of [64][64] ---
        float sacc[4][4];
        #pragma unroll
        for (int t = 0; t < 4; t++)
            #pragma unroll
            for (int r = 0; r < 4; r++) sacc[t][r] = 0.0f;

        #pragma unroll
        for (int kk = 0; kk < 8; ++kk) {
            unsigned a0, a1, a2, a3, m0, m1, m2, m3, n0, n1, n2, n3;
            ldsm4(a0, a1, a2, a3, a_q + kk * 32);
            ldsm4(m0, m1, m2, m3, b_k0 + koff + kk * 32);
            ldsm4(n0, n1, n2, n3, b_k1 + koff + kk * 32);
            mma16816(sacc[0], a0, a1, a2, a3, m0, m2);
            mma16816(sacc[1], a0, a1, a2, a3, m1, m3);
            mma16816(sacc[2], a0, a1, a2, a3, n0, n2);
            mma16816(sacc[3], a0, a1, a2, a3, n1, n3);
        }

        // --- p = mask ? exp(s*invt - invt) : 0 ; write p to g_sraw + Ps ---
        #pragma unroll
        for (int nt = 0; nt < 4; ++nt) {
            const int gcol = c * 64 + wn * 32 + nt * 8 + lq * 2;
            float p00 = mk0[nt].x ? __expf(sacc[nt][0] * invt - invt) : 0.0f;
            float p01 = mk0[nt].y ? __expf(sacc[nt][1] * invt - invt) : 0.0f;
            float p10 = mk1[nt].x ? __expf(sacc[nt][2] * invt - invt) : 0.0f;
            float p11 = mk1[nt].y ? __expf(sacc[nt][3] * invt - invt) : 0.0f;
            __half2 h0 = __floats2half2_rn(p00, p01);
            __half2 h1 = __floats2half2_rn(p10, p11);
            *reinterpret_cast<__half2*>(g_sraw + rbase0 + gcol) = h0;
            *reinterpret_cast<__half2*>(g_sraw + rbase1 + gcol) = h1;
            lsum0 += p00 + p01;
            lsum1 += p10 + p11;
            const int lr = wm * 16 + lg;
            const int lc = wn * 32 + nt * 8 + lq * 2;
            *reinterpret_cast<__half2*>(&Ps[lr * 72 + lc])       = h0;
            *reinterpret_cast<__half2*>(&Ps[(lr + 8) * 72 + lc]) = h1;
        }
        __syncthreads();     // B3: Ps ready

        // --- out += P @ V ---
        #pragma unroll
        for (int kk = 0; kk < 4; ++kk) {
            unsigned a0, a1, a2, a3;
            ldsm4(a0, a1, a2, a3, a_p + kk * 32);
            #pragma unroll
            for (int p = 0; p < 4; ++p) {
                unsigned w0, w1, w2, w3;
                ldsm4(w0, w1, w2, w3, b_v[p] + voff + kk * 32);
                mma16816(oacc[2 * p],     a0, a1, a2, a3, w0, w2);
                mma16816(oacc[2 * p + 1], a0, a1, a2, a3, w1, w3);
            }
        }
    }

    // --- reduce row sums l: over lq (shfl), then over wn (smem) ---
    lsum0 += __shfl_xor_sync(0xffffffffu, lsum0, 1);
    lsum0 += __shfl_xor_sync(0xffffffffu, lsum0, 2);
    lsum1 += __shfl_xor_sync(0xffffffffu, lsum1, 1);
    lsum1 += __shfl_xor_sync(0xffffffffu, lsum1, 2);
    __syncthreads();
    if (lq == 0) {
        sm_l[wn * 64 + wm * 16 + lg]     = lsum0;
        sm_l[wn * 64 + wm * 16 + 8 + lg] = lsum1;
    }
    __syncthreads();

    // --- epilogue: write UNNORMALIZED partial O and partial l ---
    {
        const int r0 = wm * 16 + lg;
        float* o0 = g_opart + ((size_t)z * BB * NQ + (size_t)b * NQ + q0 + r0) * DD;
        float* o1 = o0 + (size_t)8 * DD;
        #pragma unroll
        for (int nt = 0; nt < 8; ++nt) {
            const int col = wn * 64 + nt * 8 + lq * 2;
            *reinterpret_cast<float2*>(o0 + col) = make_float2(oacc[nt][0], oacc[nt][1]);
            *reinterpret_cast<float2*>(o1 + col) = make_float2(oacc[nt][2], oacc[nt][3]);
        }
        if (tid < 64)
            g_lpart[(size_t)z * BB * NQ + (size_t)b * NQ + q0 + tid] = sm_l[tid] + sm_l[64 + tid];
    }

    // --- split semaphore: last CTA of the group combines + finalizes ---
    __threadfence();
    __syncthreads();
    __shared__ int s_old;
    if (tid == 0) s_old = atomicAdd(&g_ctr[gid], 1);
    __syncthreads();
    if (s_old != NSPLIT - 1) return;
    __threadfence();

    // 1/l per row of this group
    if (tid < 64) {
        const int row = b * NQ + q0 + tid;
        const float l = g_lpart[row] + g_lpart[BB * NQ + row]
                      + g_lpart[2 * BB * NQ + row] + g_lpart[3 * BB * NQ + row];
        sm_rl[tid] = 1.0f / l;
    }
    __syncthreads();

    // out = (sum of partials) / l : 64 rows x 128 = 2048 float4
    {
        const size_t obase = ((size_t)b * NQ + q0) * DD / 4;
        const size_t ostride = (size_t)BB * NQ * DD / 4;
        const float4* op = reinterpret_cast<const float4*>(g_opart);
        #pragma unroll
        for (int i = 0; i < 8; ++i) {
            const int pos = i * 256 + tid;
            const float rl = sm_rl[pos >> 5];          // 32 float4 per row
            const size_t gi = obase + pos;
            float4 a = op[gi], e = op[gi + ostride], f = op[gi + 2 * ostride], g = op[gi + 3 * ostride];
            float4 o;
            o.x = (a.x + e.x + f.x + g.x) * rl;
            o.y = (a.y + e.y + f.y + g.y) * rl;
            o.z = (a.z + e.z + f.z + g.z) * rl;
            o.w = (a.w + e.w + f.w + g.w) * rl;
            reinterpret_cast<float4*>(outp)[gi] = o;
        }
    }

    // attn = p * (1/l) for this group's 64 rows: 64*4096 halves = 32768 uint4
    {
        const size_t pbase = ((size_t)b * NQ + q0) * NK / 8;   // uint4 index
        const uint4* sp = reinterpret_cast<const uint4*>(g_sraw);
        float4* ap = reinterpret_cast<float4*>(attnp);
        #pragma unroll 4
        for (int j = 0; j < 128; ++j) {
            const int pos = j * 256 + tid;
            const float rl = sm_rl[pos >> 9];          // 512 uint4 per row
            const size_t gi = pbase + pos;
            const uint4 rv = sp[gi];
            float2 f0 = __half22float2(*reinterpret_cast<const __half2*>(&rv.x));
            float2 f1 = __half22float2(*reinterpret_cast<const __half2*>(&rv.y));
            float2 f2 = __half22float2(*reinterpret_cast<const __half2*>(&rv.z));
            float2 f3 = __half22float2(*reinterpret_cast<const __half2*>(&rv.w));
            ap[gi * 2]     = make_float4(f0.x * rl, f0.y * rl, f1.x * rl, f1.y * rl);
            ap[gi * 2 + 1] = make_float4(f2.x * rl, f2.y * rl, f3.x * rl, f3.y * rl);
        }
    }
}

// ---------------------------------------------------------------------------
extern "C" void kernel_launch(void* const* d_in, const int* in_sizes, int n_in,
                              void* d_out, int out_size) {
    const float* q    = (const float*)d_in[0];
    const float* k    = (const float*)d_in[1];
    const float* v    = (const float*)d_in[2];
    const int*   mask = (const int*)d_in[3];
    const float* temp = (const float*)d_in[4];

    float* outp  = (float*)d_out;                            // [B,Sq,D]
    float* attnp = outp + (size_t)BB * NQ * DD;              // [B,Sq,Sk]

    prep_kernel<<<4096, 256>>>(q, k);
    vtrans_kernel<<<dim3(NK / 64, BB), 256>>>(v);
    cudaFuncSetAttribute(attn_kernel, cudaFuncAttributeMaxDynamicSharedMemorySize, SMEM_BYTES);
    // split index in blockIdx.x (fastest-varying): a group's 4 splits are
    // wave-adjacent, so group completions stagger across the whole kernel.
    attn_kernel<<<dim3(NSPLIT, NQ / 64, BB), 256, SMEM_BYTES>>>(mask, temp, outp, attnp);
}

// round 17
// speedup vs baseline: 1.8285x; 1.8285x over previous
#include <cuda_runtime.h>
#include <cuda_fp16.h>
#include <cstdint>

// Problem shape (fixed by setup_inputs)
#define BB 4
#define NQ 4096
#define NK 4096
#define DD 128
#define NSPLIT 4
#define CHUNKS_PER_SPLIT (NK / 64 / NSPLIT)   // 16

// Scratch (device globals: allocation-free rule)
__device__ __align__(16) __half g_qh[(size_t)BB * NQ * DD];   // normalized Q, fp16
__device__ __align__(16) __half g_kh[(size_t)BB * NK * DD];   // normalized K, fp16
__device__ __align__(16) __half g_vt[(size_t)BB * DD * NK];   // V transposed [b][d][k], fp16
__device__ __align__(16) __half g_sraw[(size_t)BB * NQ * NK]; // unnormalized p, fp16
__device__ __align__(16) float  g_opart[(size_t)NSPLIT * BB * NQ * DD]; // unnormalized partial O
__device__ float g_lpart[(size_t)NSPLIT * BB * NQ];           // partial row sums

// ---------------------------------------------------------------------------
// K1: L2-normalize q and k rows (warp per row), write fp16
// ---------------------------------------------------------------------------
__global__ void prep_kernel(const float* __restrict__ q, const float* __restrict__ k) {
    int gw   = (blockIdx.x * blockDim.x + threadIdx.x) >> 5;
    int lane = threadIdx.x & 31;
    const int R = BB * NQ;
    if (gw >= 2 * R) return;
    const float* src = (gw < R) ? q : k;
    __half*      dst = (gw < R) ? g_qh : g_kh;
    int row = (gw < R) ? gw : gw - R;

    float4 x = reinterpret_cast<const float4*>(src + (size_t)row * DD)[lane];
    float ss = x.x * x.x + x.y * x.y + x.z * x.z + x.w * x.w;
    #pragma unroll
    for (int o = 16; o; o >>= 1) ss += __shfl_xor_sync(0xffffffffu, ss, o);
    float sc = 1.0f / fmaxf(sqrtf(ss), 1e-12f);

    __half2* dp = reinterpret_cast<__half2*>(dst + (size_t)row * DD);
    dp[lane * 2 + 0] = __floats2half2_rn(x.x * sc, x.y * sc);
    dp[lane * 2 + 1] = __floats2half2_rn(x.z * sc, x.w * sc);
}

// ---------------------------------------------------------------------------
// K1b: transpose V (fp32 [b][k][d]) -> g_vt fp16 [b][d][k], tiles of 64 k-rows
// ---------------------------------------------------------------------------
__global__ void vtrans_kernel(const float* __restrict__ v) {
    __shared__ __half st[128][72];
    int b  = blockIdx.y;
    int k0 = blockIdx.x * 64;
    int t  = threadIdx.x;
    int kr = t >> 2, seg = t & 3;

    const float4* src = reinterpret_cast<const float4*>(v + ((size_t)b * NK + k0 + kr) * DD);
    #pragma unroll
    for (int i = 0; i < 8; i++) {
        float4 f = src[seg * 8 + i];
        int d = seg * 32 + i * 4;
        st[d + 0][kr] = __float2half_rn(f.x);
        st[d + 1][kr] = __float2half_rn(f.y);
        st[d + 2][kr] = __float2half_rn(f.z);
        st[d + 3][kr] = __float2half_rn(f.w);
    }
    __syncthreads();

    int d = t >> 1, j = t & 1;
    uint4*       dst = reinterpret_cast<uint4*>(g_vt + ((size_t)(b * 128 + d)) * NK + k0);
    const uint4* s4  = reinterpret_cast<const uint4*>(&st[d][j * 32]);
    #pragma unroll
    for (int i = 0; i < 4; i++) dst[j * 4 + i] = s4[i];
}

// ---------------------------------------------------------------------------
// PTX helpers
// ---------------------------------------------------------------------------
__device__ __forceinline__ void mma16816(float* d, unsigned a0, unsigned a1, unsigned a2,
                                         unsigned a3, unsigned b0, unsigned b1) {
    asm volatile(
        "mma.sync.aligned.m16n8k16.row.col.f32.f16.f16.f32 "
        "{%0,%1,%2,%3},{%4,%5,%6,%7},{%8,%9},{%0,%1,%2,%3};\n"
        : "+f"(d[0]), "+f"(d[1]), "+f"(d[2]), "+f"(d[3])
        : "r"(a0), "r"(a1), "r"(a2), "r"(a3), "r"(b0), "r"(b1));
}

__device__ __forceinline__ void ldsm4(unsigned& r0, unsigned& r1, unsigned& r2, unsigned& r3,
                                      uint32_t a) {
    asm volatile("ldmatrix.sync.aligned.m8n8.x4.shared.b16 {%0,%1,%2,%3},[%4];\n"
                 : "=r"(r0), "=r"(r1), "=r"(r2), "=r"(r3) : "r"(a));
}

__device__ __forceinline__ void cp16(uint32_t dst, const void* src) {
    asm volatile("cp.async.cg.shared.global [%0], [%1], 16;\n" :: "r"(dst), "l"(src));
}
__device__ __forceinline__ void cp_commit() {
    asm volatile("cp.async.commit_group;\n");
}
__device__ __forceinline__ void cp_wait1() {
    asm volatile("cp.async.wait_group 1;\n");
}

// ---------------------------------------------------------------------------
// K2: fused attention (R6 mainloop), split-K=4 via blockIdx.z (R15 winner).
// Writes unnormalized partial O and partial l; finalize combines everything.
// ---------------------------------------------------------------------------
#define KS_HALF (64 * 136)     // one K buffer, halves
#define VS_HALF (128 * 72)     // one V buffer, halves
#define SMEM_BYTES 98816

__global__ void __launch_bounds__(256, 2)
attn_kernel(const int* __restrict__ mask, const float* __restrict__ temp) {
    extern __shared__ char smem_raw[];
    __half* Qs = reinterpret_cast<__half*>(smem_raw);     // [64][136]
    __half* Ks = Qs + 64 * 136;                           // 2 x [64][136]
    __half* Vs = Ks + 2 * KS_HALF;                        // 2 x [128][72] (Vs[d][k])
    __half* Ps = Vs + 2 * VS_HALF;                        // [64][72]
    float*  sm_l = reinterpret_cast<float*>(Ps + 64 * 72);// [2][64]

    const int b  = blockIdx.y;
    const int q0 = blockIdx.x * 64;
    const int z  = blockIdx.z;
    const int c0 = z * CHUNKS_PER_SPLIT;
    const int c1 = c0 + CHUNKS_PER_SPLIT;
    const int tid  = threadIdx.x;
    const int lane = tid & 31;
    const int warp = tid >> 5;
    const int wm = warp & 3;     // 4 warps along M
    const int wn = warp >> 2;    // 2 warps along N
    const int lg = lane >> 2;    // group id 0..7
    const int lq = lane & 3;     // quad id 0..3

    const float invt = 1.0f / temp[0];

    // Load Q tile (fp16) once
    {
        int r = tid >> 2, seg = tid & 3;
        const uint4* src = reinterpret_cast<const uint4*>(g_qh + ((size_t)b * NQ + q0 + r) * DD);
        uint4* dst = reinterpret_cast<uint4*>(&Qs[r * 136 + seg * 32]);
        #pragma unroll
        for (int i = 0; i < 4; i++) dst[i] = src[seg * 4 + i];
    }

    // ldmatrix per-lane base addresses
    const int lrow = lane & 15;
    const int lcol = (lane >> 4) << 3;
    const uint32_t a_q  = (uint32_t)__cvta_generic_to_shared(&Qs[(wm * 16 + lrow) * 136 + lcol]);
    const uint32_t b_k0 = (uint32_t)__cvta_generic_to_shared(&Ks[(wn * 32 + lrow) * 136 + lcol]);
    const uint32_t b_k1 = (uint32_t)__cvta_generic_to_shared(&Ks[(wn * 32 + 16 + lrow) * 136 + lcol]);
    const uint32_t a_p  = (uint32_t)__cvta_generic_to_shared(&Ps[(wm * 16 + lrow) * 72 + lcol]);
    uint32_t b_v[4];
    #pragma unroll
    for (int p = 0; p < 4; p++)
        b_v[p] = (uint32_t)__cvta_generic_to_shared(&Vs[(wn * 64 + p * 16 + lrow) * 72 + lcol]);

    // cp.async staging addresses
    const int kr  = tid >> 2, kseg = tid & 3;
    const uint32_t ks_dst = (uint32_t)__cvta_generic_to_shared(&Ks[kr * 136 + kseg * 32]);
    const int vd = tid >> 1, vj = tid & 1;
    const uint32_t vs_dst = (uint32_t)__cvta_generic_to_shared(&Vs[vd * 72 + vj * 32]);

    const __half* gk  = g_kh + (size_t)b * NK * DD;
    const __half* gvt = g_vt + ((size_t)b * DD + vd) * NK;

    const int grow0 = q0 + wm * 16 + lg;
    const size_t rbase0 = ((size_t)b * NQ + grow0) * NK;
    const size_t rbase1 = rbase0 + (size_t)8 * NK;

    float oacc[8][4];
    #pragma unroll
    for (int t = 0; t < 8; t++)
        #pragma unroll
        for (int r = 0; r < 4; r++) oacc[t][r] = 0.0f;
    float lsum0 = 0.0f, lsum1 = 0.0f;

    // --- pipeline prologue: load chunk c0 into buffer 0 (c0 is even) ---
    {
        const __half* srcK = gk + (size_t)(c0 * 64 + kr) * DD + kseg * 32;
        #pragma unroll
        for (int i = 0; i < 4; i++) cp16(ks_dst + i * 16, srcK + i * 8);
        const __half* srcV = gvt + c0 * 64 + vj * 32;
        #pragma unroll
        for (int i = 0; i < 4; i++) cp16(vs_dst + i * 16, srcV + i * 8);
        cp_commit();
    }

    for (int c = c0; c < c1; ++c) {
        const int cur = c & 1;
        const uint32_t koff = (uint32_t)cur * (KS_HALF * 2);   // byte offsets
        const uint32_t voff = (uint32_t)cur * (VS_HALF * 2);

        __syncthreads();   // B1: buffer cur^1 free

        // --- issue loads for chunk c+1 into buffer cur^1 ---
        if (c + 1 < c1) {
            const uint32_t nkoff = (uint32_t)(cur ^ 1) * (KS_HALF * 2);
            const uint32_t nvoff = (uint32_t)(cur ^ 1) * (VS_HALF * 2);
            const __half* srcK = gk + (size_t)((c + 1) * 64 + kr) * DD + kseg * 32;
            #pragma unroll
            for (int i = 0; i < 4; i++) cp16(ks_dst + nkoff + i * 16, srcK + i * 8);
            const __half* srcV = gvt + (c + 1) * 64 + vj * 32;
            #pragma unroll
            for (int i = 0; i < 4; i++) cp16(vs_dst + nvoff + i * 16, srcV + i * 8);
        }
        cp_commit();

        // --- prefetch mask for chunk c while loads fly ---
        int2 mk0[4], mk1[4];
        #pragma unroll
        for (int nt = 0; nt < 4; ++nt) {
            const int gcol = c * 64 + wn * 32 + nt * 8 + lq * 2;
            mk0[nt] = *reinterpret_cast<const int2*>(mask + rbase0 + gcol);
            mk1[nt] = *reinterpret_cast<const int2*>(mask + rbase1 + gcol);
        }

        cp_wait1();          // chunk c resident (FIFO group completion)
        __syncthreads();     // B2: visibility across threads

        // --- S = Qn @ Kn^T : warp computes 16x32 of [64][64] ---
        float sacc[4][4];
        #pragma unroll
        for (int t = 0; t < 4; t++)
            #pragma unroll
            for (int r = 0; r < 4; r++) sacc[t][r] = 0.0f;

        #pragma unroll
        for (int kk = 0; kk < 8; ++kk) {
            unsigned a0, a1, a2, a3, m0, m1, m2, m3, n0, n1, n2, n3;
            ldsm4(a0, a1, a2, a3, a_q + kk * 32);
            ldsm4(m0, m1, m2, m3, b_k0 + koff + kk * 32);
            ldsm4(n0, n1, n2, n3, b_k1 + koff + kk * 32);
            mma16816(sacc[0], a0, a1, a2, a3, m0, m2);
            mma16816(sacc[1], a0, a1, a2, a3, m1, m3);
            mma16816(sacc[2], a0, a1, a2, a3, n0, n2);
            mma16816(sacc[3], a0, a1, a2, a3, n1, n3);
        }

        // --- p = mask ? exp(s*invt - invt) : 0 ; write p to g_sraw + Ps ---
        #pragma unroll
        for (int nt = 0; nt < 4; ++nt) {
            const int gcol = c * 64 + wn * 32 + nt * 8 + lq * 2;
            float p00 = mk0[nt].x ? __expf(sacc[nt][0] * invt - invt) : 0.0f;
            float p01 = mk0[nt].y ? __expf(sacc[nt][1] * invt - invt) : 0.0f;
            float p10 = mk1[nt].x ? __expf(sacc[nt][2] * invt - invt) : 0.0f;
            float p11 = mk1[nt].y ? __expf(sacc[nt][3] * invt - invt) : 0.0f;
            __half2 h0 = __floats2half2_rn(p00, p01);
            __half2 h1 = __floats2half2_rn(p10, p11);
            *reinterpret_cast<__half2*>(g_sraw + rbase0 + gcol) = h0;
            *reinterpret_cast<__half2*>(g_sraw + rbase1 + gcol) = h1;
            lsum0 += p00 + p01;
            lsum1 += p10 + p11;
            const int lr = wm * 16 + lg;
            const int lc = wn * 32 + nt * 8 + lq * 2;
            *reinterpret_cast<__half2*>(&Ps[lr * 72 + lc])       = h0;
            *reinterpret_cast<__half2*>(&Ps[(lr + 8) * 72 + lc]) = h1;
        }
        __syncthreads();     // B3: Ps ready

        // --- out += P @ V ---
        #pragma unroll
        for (int kk = 0; kk < 4; ++kk) {
            unsigned a0, a1, a2, a3;
            ldsm4(a0, a1, a2, a3, a_p + kk * 32);
            #pragma unroll
            for (int p = 0; p < 4; ++p) {
                unsigned w0, w1, w2, w3;
                ldsm4(w0, w1, w2, w3, b_v[p] + voff + kk * 32);
                mma16816(oacc[2 * p],     a0, a1, a2, a3, w0, w2);
                mma16816(oacc[2 * p + 1], a0, a1, a2, a3, w1, w3);
            }
        }
    }

    // --- reduce row sums l: over lq (shfl), then over wn (smem) ---
    lsum0 += __shfl_xor_sync(0xffffffffu, lsum0, 1);
    lsum0 += __shfl_xor_sync(0xffffffffu, lsum0, 2);
    lsum1 += __shfl_xor_sync(0xffffffffu, lsum1, 1);
    lsum1 += __shfl_xor_sync(0xffffffffu, lsum1, 2);
    __syncthreads();
    if (lq == 0) {
        sm_l[wn * 64 + wm * 16 + lg]     = lsum0;
        sm_l[wn * 64 + wm * 16 + 8 + lg] = lsum1;
    }
    __syncthreads();

    // --- epilogue: write UNNORMALIZED partial O and partial l ---
    {
        const int r0 = wm * 16 + lg;
        float* o0 = g_opart + ((size_t)z * BB * NQ + (size_t)b * NQ + q0 + r0) * DD;
        float* o1 = o0 + (size_t)8 * DD;
        #pragma unroll
        for (int nt = 0; nt < 8; ++nt) {
            const int col = wn * 64 + nt * 8 + lq * 2;
            *reinterpret_cast<float2*>(o0 + col) = make_float2(oacc[nt][0], oacc[nt][1]);
            *reinterpret_cast<float2*>(o1 + col) = make_float2(oacc[nt][2], oacc[nt][3]);
        }
        if (tid < 64)
            g_lpart[(size_t)z * BB * NQ + (size_t)b * NQ + q0 + tid] = sm_l[tid] + sm_l[64 + tid];
    }
}

// ---------------------------------------------------------------------------
// K3 (merged): attn = p / l for 8 elems/thread; blocks < 2048 additionally
// combine the out split-K partials (one float4 each). rl is derived per-row
// from g_lpart directly (256 KB, L2-resident) — no g_rl round-trip, no
// separate reduce launch, no inter-block ordering requirement.
// ---------------------------------------------------------------------------
__device__ __forceinline__ float row_rl(int row) {
    return 1.0f / (g_lpart[row] + g_lpart[BB * NQ + row]
                 + g_lpart[2 * BB * NQ + row] + g_lpart[3 * BB * NQ + row]);
}

__global__ void finalize_kernel(float* __restrict__ outp, float* __restrict__ attnp) {
    const size_t i = (size_t)blockIdx.x * blockDim.x + threadIdx.x;

    // --- out reduction share: first 2048 blocks, one float4 per thread ---
    if (blockIdx.x < 2048) {
        const size_t oi = i;                               // 524288 float4 total
        const size_t ostride = (size_t)BB * NQ * DD / 4;
        const float rl = row_rl((int)(oi >> 5));           // 32 float4 per row
        const float4* p = reinterpret_cast<const float4*>(g_opart);
        float4 a = p[oi], b = p[oi + ostride], c = p[oi + 2 * ostride], d = p[oi + 3 * ostride];
        float4 o;
        o.x = (a.x + b.x + c.x + d.x) * rl;
        o.y = (a.y + b.y + c.y + d.y) * rl;
        o.z = (a.z + b.z + c.z + d.z) * rl;
        o.w = (a.w + b.w + c.w + d.w) * rl;
        reinterpret_cast<float4*>(outp)[oi] = o;
    }

    // --- attn normalization: 8 elems per thread ---
    const uint4 rv = reinterpret_cast<const uint4*>(g_sraw)[i];
    const float rl = row_rl((int)(i >> 9));                // 512 uint4-units per row

    float2 f0 = __half22float2(*reinterpret_cast<const __half2*>(&rv.x));
    float2 f1 = __half22float2(*reinterpret_cast<const __half2*>(&rv.y));
    float2 f2 = __half22float2(*reinterpret_cast<const __half2*>(&rv.z));
    float2 f3 = __half22float2(*reinterpret_cast<const __half2*>(&rv.w));

    float4 o0, o1;
    o0.x = f0.x * rl; o0.y = f0.y * rl;
    o0.z = f1.x * rl; o0.w = f1.y * rl;
    o1.x = f2.x * rl; o1.y = f2.y * rl;
    o1.z = f3.x * rl; o1.w = f3.y * rl;

    float4* dst = reinterpret_cast<float4*>(attnp) + i * 2;
    dst[0] = o0;
    dst[1] = o1;
}

// ---------------------------------------------------------------------------
extern "C" void kernel_launch(void* const* d_in, const int* in_sizes, int n_in,
                              void* d_out, int out_size) {
    const float* q    = (const float*)d_in[0];
    const float* k    = (const float*)d_in[1];
    const float* v    = (const float*)d_in[2];
    const int*   mask = (const int*)d_in[3];
    const float* temp = (const float*)d_in[4];

    float* outp  = (float*)d_out;                            // [B,Sq,D]
    float* attnp = outp + (size_t)BB * NQ * DD;              // [B,Sq,Sk]

    prep_kernel<<<4096, 256>>>(q, k);
    vtrans_kernel<<<dim3(NK / 64, BB), 256>>>(v);
    cudaFuncSetAttribute(attn_kernel, cudaFuncAttributeMaxDynamicSharedMemorySize, SMEM_BYTES);
    attn_kernel<<<dim3(NQ / 64, BB, NSPLIT), 256, SMEM_BYTES>>>(mask, temp);
    // merged reduce + finalize: 32768 blocks, 8 attn elems/thread;
    // blocks < 2048 also combine the out partials.
    finalize_kernel<<<32768, 256>>>(outp, attnp);
}